// round 14
// baseline (speedup 1.0000x reference)
#include <cuda_runtime.h>

#define NMAX 100000

// Aggregation buffer agg[dst] = sum_e w_e * x_src[src_e]; 25.6 MB static.
static __device__ __align__(16) float g_agg[NMAX * 64];

// ---------------------------------------------------------------------------
// Edge scatter, dst-range predicated: for edges with dst in [dlo,dhi):
//   g_agg[dst] += x_src[src] * w.
// Proven structure (folded dtype detect, 8 edges/thread, 16 lanes/edge,
// v4 REDs, no smem). Scans all edge dsts; gathers/REDs only its range.
// ---------------------------------------------------------------------------
__global__ void __launch_bounds__(256) scatter_range_kernel(
    const float* __restrict__ xsrc,
    const void* __restrict__ ei_raw,    // [2, E]: src row then dst row
    const float* __restrict__ ew,       // [E]
    int E, int n_src, int dlo, int dhi)
{
    // dtype detect (JAX demotes int64->int32 when x64 off): warp 0 samples
    // 32 int64 slots (in-bounds under both layouts); int32 pairs have random
    // high words -> out of [0, n_src).
    __shared__ int sflag;
    {
        const long long* ei = (const long long*)ei_raw;
        if (threadIdx.x < 32) {
            long long stride = (E > 32) ? (E / 32) : 1;
            long long idx = (long long)threadIdx.x * stride;
            if (idx > E - 1) idx = E - 1;
            long long v = ei[idx];
            bool bad = (v < 0 || v >= n_src);
            unsigned m = __ballot_sync(0xffffffffu, bad);
            if (threadIdx.x == 0) sflag = (m == 0) ? 1 : 0;
        }
        __syncthreads();
    }
    const int is64 = sflag;

    const long long t = (long long)blockIdx.x * blockDim.x + threadIdx.x;
    const int lane = (int)(t & 15);
    const long long e0 = (t >> 4) * 8;
    if (e0 >= E) return;
    const int n = (E - e0 >= 8) ? 8 : (int)(E - e0);

    int d[8];
    if (is64) {
        const long long* ei = (const long long*)ei_raw;
        #pragma unroll
        for (int i = 0; i < 8; i++) if (i < n)
            d[i] = (int)ei[(long long)E + e0 + i];
    } else {
        const int* ei = (const int*)ei_raw;
        #pragma unroll
        for (int i = 0; i < 8; i++) if (i < n)
            d[i] = ei[(long long)E + e0 + i];
    }

    bool act[8];
    #pragma unroll
    for (int i = 0; i < 8; i++)
        act[i] = (i < n) && (d[i] >= dlo) && (d[i] < dhi);

    int s[8];
    float w[8];
    if (is64) {
        const long long* ei = (const long long*)ei_raw;
        #pragma unroll
        for (int i = 0; i < 8; i++) if (act[i]) s[i] = (int)ei[e0 + i];
    } else {
        const int* ei = (const int*)ei_raw;
        #pragma unroll
        for (int i = 0; i < 8; i++) if (act[i]) s[i] = ei[e0 + i];
    }
    #pragma unroll
    for (int i = 0; i < 8; i++) if (act[i]) w[i] = ew[e0 + i];

    float4 v[8];
    #pragma unroll
    for (int i = 0; i < 8; i++) if (act[i])
        v[i] = *(const float4*)(xsrc + (size_t)s[i] * 64 + lane * 4);

    #pragma unroll
    for (int i = 0; i < 8; i++) if (act[i]) {
        const float wi = w[i];
        float4 vv = v[i];
        vv.x *= wi; vv.y *= wi; vv.z *= wi; vv.w *= wi;
        float* dst = g_agg + (size_t)d[i] * 64 + lane * 4;
        asm volatile("red.global.add.v4.f32 [%0], {%1, %2, %3, %4};"
                     :: "l"(dst), "f"(vv.x), "f"(vv.y), "f"(vv.z), "f"(vv.w)
                     : "memory");
    }
}

// ---------------------------------------------------------------------------
// tf32 / cp.async helpers (proven round-12 GEMM body)
// ---------------------------------------------------------------------------
__device__ __forceinline__ unsigned f2tf32(float x) {
    unsigned u;
    asm("cvt.rna.tf32.f32 %0, %1;" : "=r"(u) : "f"(x));
    return u;
}

#define MMA_TF32(c0, c1, c2, c3, a0, a1, a2, a3, b0, b1)                     \
    asm volatile(                                                            \
        "mma.sync.aligned.m16n8k8.row.col.f32.tf32.tf32.f32 "               \
        "{%0,%1,%2,%3}, {%4,%5,%6,%7}, {%8,%9}, {%0,%1,%2,%3};"             \
        : "+f"(c0), "+f"(c1), "+f"(c2), "+f"(c3)                             \
        : "r"(a0), "r"(a1), "r"(a2), "r"(a3), "r"(b0), "r"(b1))

#define CP_ASYNC_16(smem_u32, gptr, szreg)                                   \
    asm volatile("cp.async.ca.shared.global [%0], [%1], 16, %2;"             \
                 :: "r"(smem_u32), "l"(gptr), "r"(szreg))
#define CP_ASYNC_COMMIT()  asm volatile("cp.async.commit_group;")
#define CP_ASYNC_WAIT0()   asm volatile("cp.async.wait_group 0;")

#define AS_STRIDE 68
#define BS_STRIDE 68
#define AS_FLOATS (128 * AS_STRIDE)
#define BS_FLOATS (64 * BS_STRIDE)
#define GEMM_SMEM_BYTES ((AS_FLOATS + BS_FLOATS) * 4)   // 52224 B

// Single-half tf32 GEMM body: acc (+)= A[rowbase..][0..64) @ W^T.
__device__ __forceinline__ void gemm_half_body(
    float* As, float* Bs, const float* __restrict__ A, const float* __restrict__ W,
    int rowbase, int N, int wr, int g, int tg, int tid, float acc[8][4])
{
    const unsigned as_base = (unsigned)__cvta_generic_to_shared(As);

    #pragma unroll
    for (int i = 0; i < 8; i++) {
        int f  = tid + i * 256;
        int r  = f >> 4;
        int k4 = f & 15;
        int gr = rowbase + r;
        bool ok = gr < N;
        const float* src = A + (size_t)(ok ? gr : 0) * 64 + k4 * 4;
        unsigned dst = as_base + (unsigned)(r * AS_STRIDE + k4 * 4) * 4u;
        int sz = ok ? 16 : 0;
        CP_ASYNC_16(dst, src, sz);
    }
    CP_ASYNC_COMMIT();

    #pragma unroll
    for (int i = 0; i < 4; i++) {
        int f  = tid + i * 256;
        int c  = f >> 4;
        int k4 = f & 15;
        float4 v = *(const float4*)(W + c * 64 + k4 * 4);
        float* b = Bs + c * BS_STRIDE + k4 * 4;
        b[0] = __uint_as_float(f2tf32(v.x));
        b[1] = __uint_as_float(f2tf32(v.y));
        b[2] = __uint_as_float(f2tf32(v.z));
        b[3] = __uint_as_float(f2tf32(v.w));
    }

    CP_ASYNC_WAIT0();
    __syncthreads();

    #pragma unroll
    for (int kc = 0; kc < 8; kc++) {
        const int k0 = kc * 8;
        const float* arow0 = As + (wr + g) * AS_STRIDE + k0;
        const float* arow1 = arow0 + 8 * AS_STRIDE;
        unsigned a0 = f2tf32(arow0[tg]);
        unsigned a1 = f2tf32(arow1[tg]);
        unsigned a2 = f2tf32(arow0[tg + 4]);
        unsigned a3 = f2tf32(arow1[tg + 4]);
        #pragma unroll
        for (int nt = 0; nt < 8; nt++) {
            const float* brow = Bs + (nt * 8 + g) * BS_STRIDE + k0;
            unsigned b0 = __float_as_uint(brow[tg]);
            unsigned b1 = __float_as_uint(brow[tg + 4]);
            MMA_TF32(acc[nt][0], acc[nt][1], acc[nt][2], acc[nt][3],
                     a0, a1, a2, a3, b0, b1);
        }
    }
}

// ---------------------------------------------------------------------------
// Self GEMM: out = x_dst @ W_self^T + b  (plain stores)
// ---------------------------------------------------------------------------
__global__ void __launch_bounds__(256) self_gemm_kernel(
    const float* __restrict__ Xd, const float* __restrict__ Wself,
    const float* __restrict__ bias, float* __restrict__ out, int N)
{
    extern __shared__ __align__(16) float smem[];
    float* As = smem;
    float* Bs = smem + AS_FLOATS;

    const int tid  = threadIdx.x;
    const int lane = tid & 31;
    const int wid  = tid >> 5;
    const int g    = lane >> 2;
    const int tg   = lane & 3;
    const int wr   = wid * 16;
    const int rowbase = blockIdx.x * 128;

    float acc[8][4];
    #pragma unroll
    for (int nt = 0; nt < 8; nt++) {
        float b0 = bias[nt * 8 + 2 * tg];
        float b1 = bias[nt * 8 + 2 * tg + 1];
        acc[nt][0] = b0; acc[nt][1] = b1;
        acc[nt][2] = b0; acc[nt][3] = b1;
    }

    gemm_half_body(As, Bs, Xd, Wself, rowbase, N, wr, g, tg, tid, acc);

    const int r0 = rowbase + wr + g;
    const int r1 = r0 + 8;
    if (r0 < N) {
        float* yrow = out + (size_t)r0 * 64;
        #pragma unroll
        for (int nt = 0; nt < 8; nt++)
            *(float2*)(yrow + nt * 8 + 2 * tg) = make_float2(acc[nt][0], acc[nt][1]);
    }
    if (r1 < N) {
        float* yrow = out + (size_t)r1 * 64;
        #pragma unroll
        for (int nt = 0; nt < 8; nt++)
            *(float2*)(yrow + nt * 8 + 2 * tg) = make_float2(acc[nt][2], acc[nt][3]);
    }
}

// ---------------------------------------------------------------------------
// Neighbor GEMM for a tile range: out[tiles tstart+bid] += agg @ W_nei^T
// ---------------------------------------------------------------------------
__global__ void __launch_bounds__(256) nei_gemm_q_kernel(
    const float* __restrict__ Wnei, float* __restrict__ out, int N, int tstart)
{
    extern __shared__ __align__(16) float smem[];
    float* As = smem;
    float* Bs = smem + AS_FLOATS;

    const int tid  = threadIdx.x;
    const int lane = tid & 31;
    const int wid  = tid >> 5;
    const int g    = lane >> 2;
    const int tg   = lane & 3;
    const int wr   = wid * 16;
    const int rowbase = (tstart + blockIdx.x) * 128;

    float acc[8][4];
    #pragma unroll
    for (int nt = 0; nt < 8; nt++)
        acc[nt][0] = acc[nt][1] = acc[nt][2] = acc[nt][3] = 0.f;

    gemm_half_body(As, Bs, g_agg, Wnei, rowbase, N, wr, g, tg, tid, acc);

    const int r0 = rowbase + wr + g;
    const int r1 = r0 + 8;
    if (r0 < N) {
        float* yrow = out + (size_t)r0 * 64;
        #pragma unroll
        for (int nt = 0; nt < 8; nt++) {
            float2 yv = *(float2*)(yrow + nt * 8 + 2 * tg);
            yv.x += acc[nt][0]; yv.y += acc[nt][1];
            *(float2*)(yrow + nt * 8 + 2 * tg) = yv;
        }
    }
    if (r1 < N) {
        float* yrow = out + (size_t)r1 * 64;
        #pragma unroll
        for (int nt = 0; nt < 8; nt++) {
            float2 yv = *(float2*)(yrow + nt * 8 + 2 * tg);
            yv.x += acc[nt][2]; yv.y += acc[nt][3];
            *(float2*)(yrow + nt * 8 + 2 * tg) = yv;
        }
    }
}

// ---------------------------------------------------------------------------
// Inputs: 0:x_src f32[Ns*64] 1:x_dst f32[Nd*64] 2:edge_index[2E] (i32/i64)
//         3:edge_weight f32[E] 4:W_nei [64,64] 5:W_self [64,64] 6:b_self [64]
// Output: f32 [Nd*64]
//
// DAG (fork/join via events -> concurrent in the captured graph):
//   stream0: memset(agg) -> scatter_q0 -> q1 -> q2 -> q3 ---------+-> join
//   stream2: self_gemm ; nei_q0(after q0) .. nei_q3(after q3) ----+
// ---------------------------------------------------------------------------
extern "C" void kernel_launch(void* const* d_in, const int* in_sizes, int n_in,
                              void* d_out, int out_size)
{
    const float* x_src  = (const float*)d_in[0];
    const float* x_dst  = (const float*)d_in[1];
    const void*  ei     = d_in[2];
    const float* ew     = (const float*)d_in[3];
    const float* W_nei  = (const float*)d_in[4];
    const float* W_self = (const float*)d_in[5];
    const float* b_self = (const float*)d_in[6];
    float*       out    = (float*)d_out;

    const int n_src = in_sizes[0] / 64;
    const int n_dst = in_sizes[1] / 64;
    const int E     = in_sizes[3];

    float* aggp = nullptr;
    cudaGetSymbolAddress((void**)&aggp, g_agg);

    static cudaStream_t s2;
    static cudaEvent_t ev0, eq[4], evEnd;
    static int inited = 0;
    if (!inited) {
        cudaStreamCreateWithFlags(&s2, cudaStreamNonBlocking);
        cudaEventCreateWithFlags(&ev0, cudaEventDisableTiming);
        for (int q = 0; q < 4; q++)
            cudaEventCreateWithFlags(&eq[q], cudaEventDisableTiming);
        cudaEventCreateWithFlags(&evEnd, cudaEventDisableTiming);
        cudaFuncSetAttribute(self_gemm_kernel,
                             cudaFuncAttributeMaxDynamicSharedMemorySize,
                             GEMM_SMEM_BYTES);
        cudaFuncSetAttribute(nei_gemm_q_kernel,
                             cudaFuncAttributeMaxDynamicSharedMemorySize,
                             GEMM_SMEM_BYTES);
        inited = 1;
    }

    const int ntiles = (n_dst + 127) / 128;
    int tq[5];
    for (int q = 0; q <= 4; q++) tq[q] = (ntiles * q) / 4;

    // Fork: self-GEMM on s2 runs concurrently with memset+scatter.
    cudaEventRecord(ev0, 0);
    cudaStreamWaitEvent(s2, ev0, 0);
    self_gemm_kernel<<<ntiles, 256, GEMM_SMEM_BYTES, s2>>>(
        x_dst, W_self, b_self, out, n_dst);

    // Stream 0: zero agg, then 4 dst-range scatter passes.
    cudaMemsetAsync(aggp, 0, (size_t)n_dst * 64 * sizeof(float), 0);
    {
        long long groups  = ((long long)E + 7) / 8;
        long long threads = groups * 16;
        int blocks = (int)((threads + 255) / 256);
        for (int q = 0; q < 4; q++) {
            int dlo = tq[q] * 128;
            int dhi = tq[q + 1] * 128;
            if (dhi > n_dst) dhi = n_dst;
            scatter_range_kernel<<<blocks, 256, 0, 0>>>(
                x_src, ei, ew, E, n_src, dlo, dhi);
            cudaEventRecord(eq[q], 0);
        }
    }

    // s2: per-quarter neighbor GEMM as soon as its scatter quarter is done.
    for (int q = 0; q < 4; q++) {
        cudaStreamWaitEvent(s2, eq[q], 0);
        int nb = tq[q + 1] - tq[q];
        if (nb > 0)
            nei_gemm_q_kernel<<<nb, 256, GEMM_SMEM_BYTES, s2>>>(
                W_nei, out, n_dst, tq[q]);
    }

    // Join back to the captured origin stream.
    cudaEventRecord(evEnd, s2);
    cudaStreamWaitEvent(0, evEnd, 0);
}

// round 15
// speedup vs baseline: 1.8258x; 1.8258x over previous
#include <cuda_runtime.h>

#define NMAX 100000

// Aggregation buffer agg[dst] = sum_e w_e * x_src[src_e]; 25.6 MB static.
static __device__ __align__(16) float g_agg[NMAX * 64];

// ---------------------------------------------------------------------------
// Edge scatter (input space): g_agg[dst] += x_src[src] * w.
// PROVEN round-9 structure (65us, REDG lane-rate floor): folded dtype
// detect, 8 edges/thread, 16 lanes/edge, v4 REDs, no dynamic smem.
// ---------------------------------------------------------------------------
__global__ void __launch_bounds__(256) scatter_kernel(
    const float* __restrict__ xsrc,
    const void* __restrict__ ei_raw,    // [2, E]: src row then dst row
    const float* __restrict__ ew,       // [E]
    int E, int n_src)
{
    // dtype detect (JAX demotes int64->int32 when x64 off): warp 0 samples
    // 32 int64 slots (in-bounds under both layouts); int32 pairs have random
    // high words -> out of [0, n_src).
    __shared__ int sflag;
    {
        const long long* ei = (const long long*)ei_raw;
        if (threadIdx.x < 32) {
            long long stride = (E > 32) ? (E / 32) : 1;
            long long idx = (long long)threadIdx.x * stride;
            if (idx > E - 1) idx = E - 1;
            long long v = ei[idx];
            bool bad = (v < 0 || v >= n_src);
            unsigned m = __ballot_sync(0xffffffffu, bad);
            if (threadIdx.x == 0) sflag = (m == 0) ? 1 : 0;
        }
        __syncthreads();
    }
    const int is64 = sflag;

    const long long t = (long long)blockIdx.x * blockDim.x + threadIdx.x;
    const int lane = (int)(t & 15);
    const long long e0 = (t >> 4) * 8;
    if (e0 >= E) return;
    const int n = (E - e0 >= 8) ? 8 : (int)(E - e0);

    int s[8], d[8];
    float w[8];
    if (is64) {
        const long long* ei = (const long long*)ei_raw;
        #pragma unroll
        for (int i = 0; i < 8; i++) if (i < n) {
            s[i] = (int)ei[e0 + i];
            d[i] = (int)ei[(long long)E + e0 + i];
        }
    } else {
        const int* ei = (const int*)ei_raw;
        #pragma unroll
        for (int i = 0; i < 8; i++) if (i < n) {
            s[i] = ei[e0 + i];
            d[i] = ei[(long long)E + e0 + i];
        }
    }
    #pragma unroll
    for (int i = 0; i < 8; i++) if (i < n) w[i] = ew[e0 + i];

    float4 v[8];
    #pragma unroll
    for (int i = 0; i < 8; i++) if (i < n)
        v[i] = *(const float4*)(xsrc + (size_t)s[i] * 64 + lane * 4);

    #pragma unroll
    for (int i = 0; i < 8; i++) if (i < n) {
        const float wi = w[i];
        float4 vv = v[i];
        vv.x *= wi; vv.y *= wi; vv.z *= wi; vv.w *= wi;
        float* dst = g_agg + (size_t)d[i] * 64 + lane * 4;
        asm volatile("red.global.add.v4.f32 [%0], {%1, %2, %3, %4};"
                     :: "l"(dst), "f"(vv.x), "f"(vv.y), "f"(vv.z), "f"(vv.w)
                     : "memory");
    }
}

// ---------------------------------------------------------------------------
// tf32 / cp.async helpers (proven GEMM body)
// ---------------------------------------------------------------------------
__device__ __forceinline__ unsigned f2tf32(float x) {
    unsigned u;
    asm("cvt.rna.tf32.f32 %0, %1;" : "=r"(u) : "f"(x));
    return u;
}

#define MMA_TF32(c0, c1, c2, c3, a0, a1, a2, a3, b0, b1)                     \
    asm volatile(                                                            \
        "mma.sync.aligned.m16n8k8.row.col.f32.tf32.tf32.f32 "               \
        "{%0,%1,%2,%3}, {%4,%5,%6,%7}, {%8,%9}, {%0,%1,%2,%3};"             \
        : "+f"(c0), "+f"(c1), "+f"(c2), "+f"(c3)                             \
        : "r"(a0), "r"(a1), "r"(a2), "r"(a3), "r"(b0), "r"(b1))

#define CP_ASYNC_16(smem_u32, gptr, szreg)                                   \
    asm volatile("cp.async.ca.shared.global [%0], [%1], 16, %2;"             \
                 :: "r"(smem_u32), "l"(gptr), "r"(szreg))
#define CP_ASYNC_COMMIT()  asm volatile("cp.async.commit_group;")
#define CP_ASYNC_WAIT0()   asm volatile("cp.async.wait_group 0;")

#define AS_STRIDE 68
#define BS_STRIDE 68
#define AS_FLOATS (128 * AS_STRIDE)
#define BS_FLOATS (64 * BS_STRIDE)
#define GEMM_SMEM_BYTES ((AS_FLOATS + BS_FLOATS) * 4)   // 52224 B

// Single-half tf32 GEMM body: acc (+)= A[rowbase..][0..64) @ W^T.
__device__ __forceinline__ void gemm_half_body(
    float* As, float* Bs, const float* __restrict__ A, const float* __restrict__ W,
    int rowbase, int N, int wr, int g, int tg, int tid, float acc[8][4])
{
    const unsigned as_base = (unsigned)__cvta_generic_to_shared(As);

    #pragma unroll
    for (int i = 0; i < 8; i++) {
        int f  = tid + i * 256;
        int r  = f >> 4;
        int k4 = f & 15;
        int gr = rowbase + r;
        bool ok = gr < N;
        const float* src = A + (size_t)(ok ? gr : 0) * 64 + k4 * 4;
        unsigned dst = as_base + (unsigned)(r * AS_STRIDE + k4 * 4) * 4u;
        int sz = ok ? 16 : 0;
        CP_ASYNC_16(dst, src, sz);
    }
    CP_ASYNC_COMMIT();

    #pragma unroll
    for (int i = 0; i < 4; i++) {
        int f  = tid + i * 256;
        int c  = f >> 4;
        int k4 = f & 15;
        float4 v = *(const float4*)(W + c * 64 + k4 * 4);
        float* b = Bs + c * BS_STRIDE + k4 * 4;
        b[0] = __uint_as_float(f2tf32(v.x));
        b[1] = __uint_as_float(f2tf32(v.y));
        b[2] = __uint_as_float(f2tf32(v.z));
        b[3] = __uint_as_float(f2tf32(v.w));
    }

    CP_ASYNC_WAIT0();
    __syncthreads();

    #pragma unroll
    for (int kc = 0; kc < 8; kc++) {
        const int k0 = kc * 8;
        const float* arow0 = As + (wr + g) * AS_STRIDE + k0;
        const float* arow1 = arow0 + 8 * AS_STRIDE;
        unsigned a0 = f2tf32(arow0[tg]);
        unsigned a1 = f2tf32(arow1[tg]);
        unsigned a2 = f2tf32(arow0[tg + 4]);
        unsigned a3 = f2tf32(arow1[tg + 4]);
        #pragma unroll
        for (int nt = 0; nt < 8; nt++) {
            const float* brow = Bs + (nt * 8 + g) * BS_STRIDE + k0;
            unsigned b0 = __float_as_uint(brow[tg]);
            unsigned b1 = __float_as_uint(brow[tg + 4]);
            MMA_TF32(acc[nt][0], acc[nt][1], acc[nt][2], acc[nt][3],
                     a0, a1, a2, a3, b0, b1);
        }
    }
}

// ---------------------------------------------------------------------------
// Self GEMM: out = x_dst @ W_self^T + b  (plain stores)
// ---------------------------------------------------------------------------
__global__ void __launch_bounds__(256) self_gemm_kernel(
    const float* __restrict__ Xd, const float* __restrict__ Wself,
    const float* __restrict__ bias, float* __restrict__ out, int N)
{
    extern __shared__ __align__(16) float smem[];
    float* As = smem;
    float* Bs = smem + AS_FLOATS;

    const int tid  = threadIdx.x;
    const int lane = tid & 31;
    const int wid  = tid >> 5;
    const int g    = lane >> 2;
    const int tg   = lane & 3;
    const int wr   = wid * 16;
    const int rowbase = blockIdx.x * 128;

    float acc[8][4];
    #pragma unroll
    for (int nt = 0; nt < 8; nt++) {
        float b0 = bias[nt * 8 + 2 * tg];
        float b1 = bias[nt * 8 + 2 * tg + 1];
        acc[nt][0] = b0; acc[nt][1] = b1;
        acc[nt][2] = b0; acc[nt][3] = b1;
    }

    gemm_half_body(As, Bs, Xd, Wself, rowbase, N, wr, g, tg, tid, acc);

    const int r0 = rowbase + wr + g;
    const int r1 = r0 + 8;
    if (r0 < N) {
        float* yrow = out + (size_t)r0 * 64;
        #pragma unroll
        for (int nt = 0; nt < 8; nt++)
            *(float2*)(yrow + nt * 8 + 2 * tg) = make_float2(acc[nt][0], acc[nt][1]);
    }
    if (r1 < N) {
        float* yrow = out + (size_t)r1 * 64;
        #pragma unroll
        for (int nt = 0; nt < 8; nt++)
            *(float2*)(yrow + nt * 8 + 2 * tg) = make_float2(acc[nt][2], acc[nt][3]);
    }
}

// ---------------------------------------------------------------------------
// Neighbor GEMM: out += g_agg @ W_nei^T  (RMW stores)
// ---------------------------------------------------------------------------
__global__ void __launch_bounds__(256) nei_gemm_kernel(
    const float* __restrict__ Wnei, float* __restrict__ out, int N)
{
    extern __shared__ __align__(16) float smem[];
    float* As = smem;
    float* Bs = smem + AS_FLOATS;

    const int tid  = threadIdx.x;
    const int lane = tid & 31;
    const int wid  = tid >> 5;
    const int g    = lane >> 2;
    const int tg   = lane & 3;
    const int wr   = wid * 16;
    const int rowbase = blockIdx.x * 128;

    float acc[8][4];
    #pragma unroll
    for (int nt = 0; nt < 8; nt++)
        acc[nt][0] = acc[nt][1] = acc[nt][2] = acc[nt][3] = 0.f;

    gemm_half_body(As, Bs, g_agg, Wnei, rowbase, N, wr, g, tg, tid, acc);

    const int r0 = rowbase + wr + g;
    const int r1 = r0 + 8;
    if (r0 < N) {
        float* yrow = out + (size_t)r0 * 64;
        #pragma unroll
        for (int nt = 0; nt < 8; nt++) {
            float2 yv = *(float2*)(yrow + nt * 8 + 2 * tg);
            yv.x += acc[nt][0]; yv.y += acc[nt][1];
            *(float2*)(yrow + nt * 8 + 2 * tg) = yv;
        }
    }
    if (r1 < N) {
        float* yrow = out + (size_t)r1 * 64;
        #pragma unroll
        for (int nt = 0; nt < 8; nt++) {
            float2 yv = *(float2*)(yrow + nt * 8 + 2 * tg);
            yv.x += acc[nt][2]; yv.y += acc[nt][3];
            *(float2*)(yrow + nt * 8 + 2 * tg) = yv;
        }
    }
}

// ---------------------------------------------------------------------------
// Inputs: 0:x_src f32[Ns*64] 1:x_dst f32[Nd*64] 2:edge_index[2E] (i32/i64)
//         3:edge_weight f32[E] 4:W_nei [64,64] 5:W_self [64,64] 6:b_self [64]
// Output: f32 [Nd*64]
//
// DAG: stream0: memset -> scatter ----------------+-> (join via s2)
//      s2:      self_gemm (concurrent w/ scatter) -+-> nei_gemm -> join
// ---------------------------------------------------------------------------
extern "C" void kernel_launch(void* const* d_in, const int* in_sizes, int n_in,
                              void* d_out, int out_size)
{
    const float* x_src  = (const float*)d_in[0];
    const float* x_dst  = (const float*)d_in[1];
    const void*  ei     = d_in[2];
    const float* ew     = (const float*)d_in[3];
    const float* W_nei  = (const float*)d_in[4];
    const float* W_self = (const float*)d_in[5];
    const float* b_self = (const float*)d_in[6];
    float*       out    = (float*)d_out;

    const int n_src = in_sizes[0] / 64;
    const int n_dst = in_sizes[1] / 64;
    const int E     = in_sizes[3];

    float* aggp = nullptr;
    cudaGetSymbolAddress((void**)&aggp, g_agg);

    static cudaStream_t s2;
    static cudaEvent_t evStart, evScat, evEnd;
    static int inited = 0;
    if (!inited) {
        cudaStreamCreateWithFlags(&s2, cudaStreamNonBlocking);
        cudaEventCreateWithFlags(&evStart, cudaEventDisableTiming);
        cudaEventCreateWithFlags(&evScat,  cudaEventDisableTiming);
        cudaEventCreateWithFlags(&evEnd,   cudaEventDisableTiming);
        cudaFuncSetAttribute(self_gemm_kernel,
                             cudaFuncAttributeMaxDynamicSharedMemorySize,
                             GEMM_SMEM_BYTES);
        cudaFuncSetAttribute(nei_gemm_kernel,
                             cudaFuncAttributeMaxDynamicSharedMemorySize,
                             GEMM_SMEM_BYTES);
        inited = 1;
    }

    const int ntiles = (n_dst + 127) / 128;

    // Fork: self-GEMM on s2, concurrent with memset+scatter on stream0.
    cudaEventRecord(evStart, 0);
    cudaStreamWaitEvent(s2, evStart, 0);
    self_gemm_kernel<<<ntiles, 256, GEMM_SMEM_BYTES, s2>>>(
        x_dst, W_self, b_self, out, n_dst);

    // stream0: zero agg, then the single proven scatter.
    cudaMemsetAsync(aggp, 0, (size_t)n_dst * 64 * sizeof(float), 0);
    {
        long long groups  = ((long long)E + 7) / 8;
        long long threads = groups * 16;
        int blocks = (int)((threads + 255) / 256);
        scatter_kernel<<<blocks, 256, 0, 0>>>(x_src, ei, ew, E, n_src);
    }
    cudaEventRecord(evScat, 0);

    // s2: nei-GEMM after scatter (and after self_gemm, same stream).
    cudaStreamWaitEvent(s2, evScat, 0);
    nei_gemm_kernel<<<ntiles, 256, GEMM_SMEM_BYTES, s2>>>(W_nei, out, n_dst);

    // Join back to the captured origin stream.
    cudaEventRecord(evEnd, s2);
    cudaStreamWaitEvent(0, evEnd, 0);
}